// round 1
// baseline (speedup 1.0000x reference)
#include <cuda_runtime.h>

#define NCTX   4096
#define DMODEL 512
#define NBATCH 2

// Scratch: K projection and scores/probs buffer (in-place softmax).
__device__ float g_K[(size_t)NBATCH * NCTX * DMODEL];        // 16.8 MB
__device__ float g_S[(size_t)NBATCH * NCTX * NCTX];          // 134 MB

// ---------------------------------------------------------------------------
// Tiled fp32 GEMM core: C_tile(128x128) += A[m0:m0+128, k0:k1] * B'
//   BT=true : B is [N, K] row-major (compute A * B^T)
//   BT=false: B is [K, N] row-major (compute A * B)
// All dims/tile offsets are multiples of the tile sizes (guaranteed by caller).
// 256 threads, 8x8 accumulators per thread, BK=8, register prefetch.
// ---------------------------------------------------------------------------
template <bool BT>
__device__ __forceinline__ void gemm_tile(
    const float* __restrict__ A, int lda,
    const float* __restrict__ Bm, int ldb,
    int m0, int n0, int k0, int k1,
    float (&acc)[8][8])
{
    __shared__ float sA[8 * 128];
    __shared__ float sB[8 * 128];

    const int t  = threadIdx.x;
    const int ty = t >> 4;           // 0..15
    const int tx = t & 15;           // 0..15

    // A / B(transposed) staging indices: thread -> (row, 4-col half)
    const int ar = t >> 1;           // 0..127
    const int ah = (t & 1) * 4;      // 0 or 4
    // B(non-transposed) staging indices
    const int bkr  = t >> 5;         // 0..7
    const int bseg = (t & 31) * 4;   // 0..124

    const float* Aptr  = A  + (size_t)(m0 + ar) * lda + ah;
    const float* BptrT = Bm + (size_t)(n0 + ar) * ldb + ah;
    const float* BptrN = Bm + (size_t)bkr * ldb + n0 + bseg;

    float4 ra, rb;
    ra = *(const float4*)(Aptr + k0);
    if (BT) rb = *(const float4*)(BptrT + k0);
    else    rb = *(const float4*)(BptrN + (size_t)k0 * ldb);

    for (int kt = k0; kt < k1; kt += 8) {
        // stage registers -> smem (A transposed to [k][m] for broadcast reads)
        sA[(ah + 0) * 128 + ar] = ra.x;
        sA[(ah + 1) * 128 + ar] = ra.y;
        sA[(ah + 2) * 128 + ar] = ra.z;
        sA[(ah + 3) * 128 + ar] = ra.w;
        if (BT) {
            sB[(ah + 0) * 128 + ar] = rb.x;
            sB[(ah + 1) * 128 + ar] = rb.y;
            sB[(ah + 2) * 128 + ar] = rb.z;
            sB[(ah + 3) * 128 + ar] = rb.w;
        } else {
            *(float4*)&sB[bkr * 128 + bseg] = rb;
        }
        __syncthreads();

        // prefetch next k-slab while computing this one
        const int kn = kt + 8;
        if (kn < k1) {
            ra = *(const float4*)(Aptr + kn);
            if (BT) rb = *(const float4*)(BptrT + kn);
            else    rb = *(const float4*)(BptrN + (size_t)kn * ldb);
        }

        #pragma unroll
        for (int kk = 0; kk < 8; kk++) {
            float a[8], b[8];
            *(float4*)&a[0] = *(const float4*)&sA[kk * 128 + ty * 8];
            *(float4*)&a[4] = *(const float4*)&sA[kk * 128 + ty * 8 + 4];
            *(float4*)&b[0] = *(const float4*)&sB[kk * 128 + tx * 8];
            *(float4*)&b[4] = *(const float4*)&sB[kk * 128 + tx * 8 + 4];
            #pragma unroll
            for (int i = 0; i < 8; i++)
                #pragma unroll
                for (int j = 0; j < 8; j++)
                    acc[i][j] += a[i] * b[j];
        }
        __syncthreads();
    }
}

// ---------------------------------------------------------------------------
// Kernel 1: g_K = x @ W^T   (M=B*NCTX=8192, N=DMODEL=512, K=DMODEL=512)
// ---------------------------------------------------------------------------
__global__ void __launch_bounds__(256)
k_proj(const float* __restrict__ x, const float* __restrict__ W)
{
    const int m0 = blockIdx.y * 128;
    const int n0 = blockIdx.x * 128;
    float acc[8][8] = {};
    gemm_tile<true>(x, DMODEL, W, DMODEL, m0, n0, 0, DMODEL, acc);

    const int ty = threadIdx.x >> 4, tx = threadIdx.x & 15;
    #pragma unroll
    for (int i = 0; i < 8; i++) {
        float4 v0 = {acc[i][0], acc[i][1], acc[i][2], acc[i][3]};
        float4 v1 = {acc[i][4], acc[i][5], acc[i][6], acc[i][7]};
        float* c = &g_K[(size_t)(m0 + ty * 8 + i) * DMODEL + n0 + tx * 8];
        *(float4*)(c)     = v0;
        *(float4*)(c + 4) = v1;
    }
}

// ---------------------------------------------------------------------------
// Kernel 2: S[b] = x[b] @ K[b]^T, lower-triangular tiles only.
// Upper-triangle entries are never read by softmax, so no mask is needed.
// ---------------------------------------------------------------------------
__global__ void __launch_bounds__(256)
k_scores(const float* __restrict__ x)
{
    const int b  = blockIdx.z;
    const int m0 = blockIdx.y * 128;
    const int n0 = blockIdx.x * 128;
    if (n0 > m0) return;  // tile fully above the diagonal

    const float* xb = x   + (size_t)b * NCTX * DMODEL;
    const float* Kb = g_K + (size_t)b * NCTX * DMODEL;
    float*       Sb = g_S + (size_t)b * NCTX * NCTX;

    float acc[8][8] = {};
    gemm_tile<true>(xb, DMODEL, Kb, DMODEL, m0, n0, 0, DMODEL, acc);

    const int ty = threadIdx.x >> 4, tx = threadIdx.x & 15;
    #pragma unroll
    for (int i = 0; i < 8; i++) {
        float4 v0 = {acc[i][0], acc[i][1], acc[i][2], acc[i][3]};
        float4 v1 = {acc[i][4], acc[i][5], acc[i][6], acc[i][7]};
        float* c = &Sb[(size_t)(m0 + ty * 8 + i) * NCTX + n0 + tx * 8];
        *(float4*)(c)     = v0;
        *(float4*)(c + 4) = v1;
    }
}

// ---------------------------------------------------------------------------
// Kernel 3: in-place causal row softmax on g_S. Row q uses [0, q]; entries
// (q, round_up(q+1,128)) are zero-filled so the P@K GEMM can run whole tiles.
// ---------------------------------------------------------------------------
__device__ __forceinline__ float blk_reduce(float v, bool is_max)
{
    __shared__ float sm[8];
    const int lane = threadIdx.x & 31, w = threadIdx.x >> 5;
    #pragma unroll
    for (int o = 16; o; o >>= 1) {
        float u = __shfl_xor_sync(0xffffffffu, v, o);
        v = is_max ? fmaxf(v, u) : v + u;
    }
    if (lane == 0) sm[w] = v;
    __syncthreads();
    float r = sm[0];
    #pragma unroll
    for (int i = 1; i < 8; i++) r = is_max ? fmaxf(r, sm[i]) : r + sm[i];
    __syncthreads();
    return r;
}

__global__ void __launch_bounds__(256)
k_softmax()
{
    const int row = blockIdx.x;           // 0 .. B*NCTX-1
    const int q   = row & (NCTX - 1);
    float* p = g_S + (size_t)row * NCTX;
    const int len = q + 1;

    float m = -1e30f;
    for (int i = threadIdx.x; i < len; i += 256) m = fmaxf(m, p[i]);
    m = blk_reduce(m, true);

    float s = 0.f;
    for (int i = threadIdx.x; i < len; i += 256) {
        float e = __expf(p[i] - m);
        p[i] = e;
        s += e;
    }
    s = blk_reduce(s, false);
    const float inv = 1.f / s;

    for (int i = threadIdx.x; i < len; i += 256) p[i] *= inv;

    const int lenUp = (len + 127) & ~127;
    for (int i = len + threadIdx.x; i < lenUp; i += 256) p[i] = 0.f;
}

// ---------------------------------------------------------------------------
// Kernel 4: out = x + P @ K, split-K over the (causally trimmed) reduction.
// Chunk c covers k in [c*1024, min((c+1)*1024, m0+128)). out is pre-zeroed;
// chunk 0 folds in the residual. Partials combined with atomicAdd.
// ---------------------------------------------------------------------------
__global__ void __launch_bounds__(256)
k_out(const float* __restrict__ x, float* __restrict__ out)
{
    const int b  = blockIdx.z >> 2;
    const int c  = blockIdx.z & 3;
    const int m0 = blockIdx.y * 128;
    const int n0 = blockIdx.x * 128;

    const int kend = m0 + 128;           // rows of this tile only attend < kend
    const int kbeg = c * 1024;
    if (kbeg >= kend) return;
    const int k1 = kend < kbeg + 1024 ? kend : kbeg + 1024;

    const float* Pb = g_S + (size_t)b * NCTX * NCTX;
    const float* Kb = g_K + (size_t)b * NCTX * DMODEL;

    float acc[8][8] = {};
    gemm_tile<false>(Pb, NCTX, Kb, DMODEL, m0, n0, kbeg, k1, acc);

    const int ty = threadIdx.x >> 4, tx = threadIdx.x & 15;
    #pragma unroll
    for (int i = 0; i < 8; i++) {
        const size_t base = (size_t)b * NCTX * DMODEL
                          + (size_t)(m0 + ty * 8 + i) * DMODEL + n0 + tx * 8;
        #pragma unroll
        for (int j = 0; j < 8; j++) {
            float v = acc[i][j];
            if (c == 0) v += x[base + j];
            atomicAdd(&out[base + j], v);
        }
    }
}

// ---------------------------------------------------------------------------
extern "C" void kernel_launch(void* const* d_in, const int* in_sizes, int n_in,
                              void* d_out, int out_size)
{
    const float* x = (const float*)d_in[0];   // [B, NCTX, DMODEL] fp32
    const float* W = (const float*)d_in[1];   // [DMODEL, DMODEL] fp32
    float* out = (float*)d_out;               // [B, NCTX, DMODEL] fp32

    // out = 0 (d_out arrives poisoned; split-K accumulates into it)
    cudaMemsetAsync(out, 0, (size_t)out_size * sizeof(float), 0);

    // 1) K = x @ W^T
    k_proj<<<dim3(DMODEL / 128, (NBATCH * NCTX) / 128), 256>>>(x, W);

    // 2) S = x @ K^T (lower-triangular tiles)
    k_scores<<<dim3(NCTX / 128, NCTX / 128, NBATCH), 256>>>(x);

    // 3) causal softmax in place
    k_softmax<<<NBATCH * NCTX, 256>>>();

    // 4) out = x + P @ K (split-K, 4 chunks of 1024)
    k_out<<<dim3(DMODEL / 128, NCTX / 128, NBATCH * 4), 256>>>(x, out);
}

// round 3
// speedup vs baseline: 1.5378x; 1.5378x over previous
#include <cuda_runtime.h>
#include <cstdint>

#define NCTX 4096
#define DM   512
#define NB   2

// Scratch
__device__ float g_K [(size_t)NB*NCTX*DM];    // K = x @ W^T        [B*NCTX, DM]
__device__ float g_Kt[(size_t)DM*NB*NCTX];    // K^T = W @ x^T      [DM, B*NCTX]
__device__ float g_S [(size_t)NB*NCTX*NCTX];  // scores / probs     [B, NCTX, NCTX]

// ---------------------------------------------------------------------------
// helpers
// ---------------------------------------------------------------------------
__device__ __forceinline__ uint32_t s2u(const void* p){
  uint32_t a;
  asm("{ .reg .u64 t; cvta.to.shared.u64 t, %1; cvt.u32.u64 %0, t; }" : "=r"(a) : "l"(p));
  return a;
}
__device__ __forceinline__ float tf32r(float x){   // round-to-nearest tf32
  uint32_t u; asm("cvt.rna.tf32.f32 %0, %1;" : "=r"(u) : "f"(x));
  return __uint_as_float(u);
}
__device__ __forceinline__ void ldsm4(uint32_t* r, uint32_t addr){
  asm volatile("ldmatrix.sync.aligned.m8n8.x4.shared.b16 {%0,%1,%2,%3}, [%4];"
    : "=r"(r[0]), "=r"(r[1]), "=r"(r[2]), "=r"(r[3]) : "r"(addr));
}
__device__ __forceinline__ void mma8(float* c, const uint32_t* a, const uint32_t* b){
  asm volatile("mma.sync.aligned.m16n8k8.row.col.f32.tf32.tf32.f32 "
    "{%0,%1,%2,%3}, {%4,%5,%6,%7}, {%8,%9}, {%0,%1,%2,%3};"
    : "+f"(c[0]), "+f"(c[1]), "+f"(c[2]), "+f"(c[3])
    : "r"(a[0]), "r"(a[1]), "r"(a[2]), "r"(a[3]), "r"(b[0]), "r"(b[1]));
}

// ---------------------------------------------------------------------------
// Tensor-core tf32 GEMM: C[128x128 tile] = A[m0:,k0:k1] * B[n0:,k0:k1]^T
// A:[M,K] row-major, B:[N,K] row-major (both K-major). 256 threads.
// SPLIT: hi/lo tf32 3-MMA emulation of fp32.
// smem rows padded to 20 floats (80B) -> conflict-free ldmatrix.
// ---------------------------------------------------------------------------
#define TILE_B  (128*20*4)      // one operand tile (hi or lo): 10240 B
#define MFRAG_B (16*20*4)       // 16 rows: 1280 B

template<bool SPLIT, class EPI>
__device__ __forceinline__ void tc_gemm(const float* __restrict__ A, int lda,
                                        const float* __restrict__ B, int ldb,
                                        int m0, int n0, int k0, int k1, EPI&& epi)
{
  extern __shared__ __align__(16) char sd[];
  const int t = threadIdx.x, l = t & 31, w = t >> 5;
  const int wm = w & 3, wn = w >> 2;          // 4 warps on M x 2 on N
  const int NT = SPLIT ? 4 : 2;
  const int STAGE = NT * TILE_B;

  // staging indices: thread -> (row, 8-float segment)
  const int arow = t >> 1, acol = (t & 1) * 8;
  const float* Ap = A + (size_t)(m0 + arow) * lda + acol;
  const float* Bp = B + (size_t)(n0 + arow) * ldb + acol;
  const uint32_t soff = (uint32_t)(arow * 20 + acol) * 4;

  // ldmatrix per-lane offsets
  const int rowA = (l & 7) + ((l >> 3) & 1) * 8;
  const int colA = ((l >> 4) & 1) * 4;
  const int rowB = (l & 7) + ((l >> 4) & 1) * 8;
  const int colB = ((l >> 3) & 1) * 4;
  const uint32_t aoff = (uint32_t)((wm * 32 + rowA) * 20 + colA) * 4;
  const uint32_t boff = (uint32_t)((wn * 64 + rowB) * 20 + colB) * 4;
  const uint32_t sbase = s2u(sd);

  float acc[2][8][4] = {};
  float4 pa0, pa1, pb0, pb1;

  const int nch = (k1 - k0) >> 4;
  pa0 = *(const float4*)(Ap + k0);     pa1 = *(const float4*)(Ap + k0 + 4);
  pb0 = *(const float4*)(Bp + k0);     pb1 = *(const float4*)(Bp + k0 + 4);

  for (int c = 0; c < nch; c++){
    char* st = sd + (c & 1) * STAGE;
    char* pAhi = st;
    char* pAlo = st + TILE_B;
    char* pBhi = st + (SPLIT ? 2 : 1) * TILE_B;
    char* pBlo = pBhi + TILE_B;

    // cvt + STS
    float4 h0 = make_float4(tf32r(pa0.x), tf32r(pa0.y), tf32r(pa0.z), tf32r(pa0.w));
    float4 h1 = make_float4(tf32r(pa1.x), tf32r(pa1.y), tf32r(pa1.z), tf32r(pa1.w));
    *(float4*)(pAhi + soff)      = h0;
    *(float4*)(pAhi + soff + 16) = h1;
    if (SPLIT){
      *(float4*)(pAlo + soff)      = make_float4(tf32r(pa0.x-h0.x), tf32r(pa0.y-h0.y),
                                                 tf32r(pa0.z-h0.z), tf32r(pa0.w-h0.w));
      *(float4*)(pAlo + soff + 16) = make_float4(tf32r(pa1.x-h1.x), tf32r(pa1.y-h1.y),
                                                 tf32r(pa1.z-h1.z), tf32r(pa1.w-h1.w));
    }
    h0 = make_float4(tf32r(pb0.x), tf32r(pb0.y), tf32r(pb0.z), tf32r(pb0.w));
    h1 = make_float4(tf32r(pb1.x), tf32r(pb1.y), tf32r(pb1.z), tf32r(pb1.w));
    *(float4*)(pBhi + soff)      = h0;
    *(float4*)(pBhi + soff + 16) = h1;
    if (SPLIT){
      *(float4*)(pBlo + soff)      = make_float4(tf32r(pb0.x-h0.x), tf32r(pb0.y-h0.y),
                                                 tf32r(pb0.z-h0.z), tf32r(pb0.w-h0.w));
      *(float4*)(pBlo + soff + 16) = make_float4(tf32r(pb1.x-h1.x), tf32r(pb1.y-h1.y),
                                                 tf32r(pb1.z-h1.z), tf32r(pb1.w-h1.w));
    }
    __syncthreads();

    // prefetch next chunk
    if (c + 1 < nch){
      const int kn = k0 + (c + 1) * 16;
      pa0 = *(const float4*)(Ap + kn);     pa1 = *(const float4*)(Ap + kn + 4);
      pb0 = *(const float4*)(Bp + kn);     pb1 = *(const float4*)(Bp + kn + 4);
    }

    // compute from smem
    const uint32_t base = sbase + (c & 1) * STAGE;
    const uint32_t uAhi = base + aoff;
    const uint32_t uAlo = uAhi + TILE_B;
    const uint32_t uBhi = base + (SPLIT ? 2 : 1) * TILE_B + boff;
    const uint32_t uBlo = uBhi + TILE_B;

    #pragma unroll
    for (int kf = 0; kf < 2; kf++){
      const uint32_t ko = kf * 32;
      uint32_t ah[2][4], al[2][4];
      ldsm4(ah[0], uAhi + ko);
      ldsm4(ah[1], uAhi + ko + MFRAG_B);
      if (SPLIT){
        ldsm4(al[0], uAlo + ko);
        ldsm4(al[1], uAlo + ko + MFRAG_B);
      }
      #pragma unroll
      for (int nf2 = 0; nf2 < 4; nf2++){
        uint32_t bh[4];
        ldsm4(bh, uBhi + ko + nf2 * MFRAG_B);
        #pragma unroll
        for (int mf = 0; mf < 2; mf++){
          mma8(acc[mf][2*nf2],     ah[mf], bh);
          mma8(acc[mf][2*nf2 + 1], ah[mf], bh + 2);
        }
        if (SPLIT){
          uint32_t bl[4];
          ldsm4(bl, uBlo + ko + nf2 * MFRAG_B);
          #pragma unroll
          for (int mf = 0; mf < 2; mf++){
            mma8(acc[mf][2*nf2],     ah[mf], bl);
            mma8(acc[mf][2*nf2 + 1], ah[mf], bl + 2);
            mma8(acc[mf][2*nf2],     al[mf], bh);
            mma8(acc[mf][2*nf2 + 1], al[mf], bh + 2);
          }
        }
      }
    }
  }
  epi(acc);
}

// store epilogue: C[m0+.., n0+..] = acc
__device__ __forceinline__ void epi_store(float (&acc)[2][8][4],
                                          float* __restrict__ C, int ldc,
                                          int m0, int n0)
{
  const int t = threadIdx.x, l = t & 31, w = t >> 5;
  const int wm = w & 3, wn = w >> 2;
  #pragma unroll
  for (int mf = 0; mf < 2; mf++){
    const int r0 = m0 + wm*32 + mf*16 + (l >> 2);
    #pragma unroll
    for (int nf = 0; nf < 8; nf++){
      const int cc = n0 + wn*64 + nf*8 + 2*(l & 3);
      *(float2*)&C[(size_t)r0*ldc + cc]       = make_float2(acc[mf][nf][0], acc[mf][nf][1]);
      *(float2*)&C[(size_t)(r0+8)*ldc + cc]   = make_float2(acc[mf][nf][2], acc[mf][nf][3]);
    }
  }
}

// ---------------------------------------------------------------------------
// Kernels
// ---------------------------------------------------------------------------
__global__ void __launch_bounds__(256)
k_proj_a(const float* __restrict__ x, const float* __restrict__ W)
{ // g_K = x @ W^T
  const int n0 = blockIdx.x*128, m0 = blockIdx.y*128;
  tc_gemm<true>(x, DM, W, DM, m0, n0, 0, DM,
    [&](float (&acc)[2][8][4]){ epi_store(acc, g_K, DM, m0, n0); });
}

__global__ void __launch_bounds__(256)
k_proj_b(const float* __restrict__ x, const float* __restrict__ W)
{ // g_Kt = W @ x^T
  const int n0 = blockIdx.x*128, m0 = blockIdx.y*128;
  tc_gemm<true>(W, DM, x, DM, m0, n0, 0, DM,
    [&](float (&acc)[2][8][4]){ epi_store(acc, g_Kt, NB*NCTX, m0, n0); });
}

__global__ void __launch_bounds__(256)
k_scores_tc(const float* __restrict__ x)
{ // S = x @ K^T (lower-triangular tiles)
  const int b  = blockIdx.z;
  const int n0 = blockIdx.x*128, m0 = blockIdx.y*128;
  if (n0 > m0) return;
  const float* xb = x   + (size_t)b*NCTX*DM;
  const float* Kb = g_K + (size_t)b*NCTX*DM;
  float*       Sb = g_S + (size_t)b*NCTX*NCTX;
  tc_gemm<true>(xb, DM, Kb, DM, m0, n0, 0, DM,
    [&](float (&acc)[2][8][4]){ epi_store(acc, Sb, NCTX, m0, n0); });
}

__global__ void __launch_bounds__(256)
k_out_tc(const float* __restrict__ x, float* __restrict__ out)
{ // out = x + P @ K  (split-K over causal extent, atomic combine)
  const int b = blockIdx.z >> 2, cch = blockIdx.z & 3;
  const int n0 = blockIdx.x*128, m0 = blockIdx.y*128;
  const int kend = m0 + 128, kbeg = cch*1024;
  if (kbeg >= kend) return;
  const int k1 = kend < kbeg + 1024 ? kend : kbeg + 1024;
  const float* Pb = g_S  + (size_t)b*NCTX*NCTX;
  const float* Bt = g_Kt + (size_t)b*NCTX;     // [DM rows, ld NB*NCTX]
  tc_gemm<false>(Pb, NCTX, Bt, NB*NCTX, m0, n0, kbeg, k1,
    [&](float (&acc)[2][8][4]){
      const int t = threadIdx.x, l = t & 31, w = t >> 5;
      const int wm = w & 3, wn = w >> 2;
      #pragma unroll
      for (int mf = 0; mf < 2; mf++){
        const int r0 = m0 + wm*32 + mf*16 + (l >> 2);
        #pragma unroll
        for (int nf = 0; nf < 8; nf++){
          const int cc = n0 + wn*64 + nf*8 + 2*(l & 3);
          const size_t i0 = (size_t)b*NCTX*DM + (size_t)r0*DM + cc;
          const size_t i1 = i0 + (size_t)8*DM;
          float v0 = acc[mf][nf][0], v1 = acc[mf][nf][1];
          float v2 = acc[mf][nf][2], v3 = acc[mf][nf][3];
          if (cch == 0){ v0 += x[i0]; v1 += x[i0+1]; v2 += x[i1]; v3 += x[i1+1]; }
          atomicAdd(out + i0,     v0);
          atomicAdd(out + i0 + 1, v1);
          atomicAdd(out + i1,     v2);
          atomicAdd(out + i1 + 1, v3);
        }
      }
    });
}

// ---------------------------------------------------------------------------
// Causal softmax, in place on g_S
// ---------------------------------------------------------------------------
__device__ __forceinline__ float blk_reduce(float v, bool is_max)
{
  __shared__ float sm[8];
  const int lane = threadIdx.x & 31, w = threadIdx.x >> 5;
  #pragma unroll
  for (int o = 16; o; o >>= 1){
    float u = __shfl_xor_sync(0xffffffffu, v, o);
    v = is_max ? fmaxf(v, u) : v + u;
  }
  if (lane == 0) sm[w] = v;
  __syncthreads();
  float r = sm[0];
  #pragma unroll
  for (int i = 1; i < 8; i++) r = is_max ? fmaxf(r, sm[i]) : r + sm[i];
  __syncthreads();
  return r;
}

__global__ void __launch_bounds__(256)
k_softmax()
{
  const int row = blockIdx.x;
  const int q   = row & (NCTX - 1);
  float* p = g_S + (size_t)row * NCTX;
  const int len = q + 1;

  float m = -1e30f;
  for (int i = threadIdx.x; i < len; i += 256) m = fmaxf(m, p[i]);
  m = blk_reduce(m, true);

  float s = 0.f;
  for (int i = threadIdx.x; i < len; i += 256){
    float e = __expf(p[i] - m);
    p[i] = e;
    s += e;
  }
  s = blk_reduce(s, false);
  const float inv = 1.f / s;

  for (int i = threadIdx.x; i < len; i += 256) p[i] *= inv;

  const int lenUp = (len + 127) & ~127;
  for (int i = len + threadIdx.x; i < lenUp; i += 256) p[i] = 0.f;
}

// ---------------------------------------------------------------------------
extern "C" void kernel_launch(void* const* d_in, const int* in_sizes, int n_in,
                              void* d_out, int out_size)
{
  const float* x = (const float*)d_in[0];
  const float* W = (const float*)d_in[1];
  float* out = (float*)d_out;

  const int SMEM_SPLIT = 2 * 4 * TILE_B;   // 81920
  const int SMEM_PLAIN = 2 * 2 * TILE_B;   // 40960
  cudaFuncSetAttribute(k_proj_a,    cudaFuncAttributeMaxDynamicSharedMemorySize, SMEM_SPLIT);
  cudaFuncSetAttribute(k_proj_b,    cudaFuncAttributeMaxDynamicSharedMemorySize, SMEM_SPLIT);
  cudaFuncSetAttribute(k_scores_tc, cudaFuncAttributeMaxDynamicSharedMemorySize, SMEM_SPLIT);
  cudaFuncSetAttribute(k_out_tc,    cudaFuncAttributeMaxDynamicSharedMemorySize, SMEM_PLAIN);

  cudaMemsetAsync(out, 0, (size_t)out_size * sizeof(float), 0);

  k_proj_a   <<<dim3(4, 64),       256, SMEM_SPLIT>>>(x, W);
  k_proj_b   <<<dim3(64, 4),       256, SMEM_SPLIT>>>(x, W);
  k_scores_tc<<<dim3(32, 32, NB),  256, SMEM_SPLIT>>>(x);
  k_softmax  <<<NB * NCTX, 256>>>();
  k_out_tc   <<<dim3(4, 32, NB*4), 256, SMEM_PLAIN>>>(x, out);
}

// round 4
// speedup vs baseline: 1.7358x; 1.1288x over previous
#include <cuda_runtime.h>
#include <cstdint>

#define NCTX 4096
#define DM   512
#define NB   2

// Scratch
__device__ float g_K [(size_t)NB*NCTX*DM];    // K = x @ W^T        [B*NCTX, DM]
__device__ float g_Kt[(size_t)DM*NB*NCTX];    // K^T                [DM, B*NCTX]
__device__ float g_S [(size_t)NB*NCTX*NCTX];  // scores / probs     [B, NCTX, NCTX]

// ---------------------------------------------------------------------------
// helpers
// ---------------------------------------------------------------------------
__device__ __forceinline__ uint32_t s2u(const void* p){
  uint32_t a;
  asm("{ .reg .u64 t; cvta.to.shared.u64 t, %1; cvt.u32.u64 %0, t; }" : "=r"(a) : "l"(p));
  return a;
}
__device__ __forceinline__ float tf32r(float x){   // round-to-nearest tf32
  uint32_t u; asm("cvt.rna.tf32.f32 %0, %1;" : "=r"(u) : "f"(x));
  return __uint_as_float(u);
}
__device__ __forceinline__ void ldsm4(uint32_t* r, uint32_t addr){
  asm volatile("ldmatrix.sync.aligned.m8n8.x4.shared.b16 {%0,%1,%2,%3}, [%4];"
    : "=r"(r[0]), "=r"(r[1]), "=r"(r[2]), "=r"(r[3]) : "r"(addr));
}
__device__ __forceinline__ void mma8(float* c, const uint32_t* a, const uint32_t* b){
  asm volatile("mma.sync.aligned.m16n8k8.row.col.f32.tf32.tf32.f32 "
    "{%0,%1,%2,%3}, {%4,%5,%6,%7}, {%8,%9}, {%0,%1,%2,%3};"
    : "+f"(c[0]), "+f"(c[1]), "+f"(c[2]), "+f"(c[3])
    : "r"(a[0]), "r"(a[1]), "r"(a[2]), "r"(a[3]), "r"(b[0]), "r"(b[1]));
}

// ---------------------------------------------------------------------------
// Tensor-core tf32 GEMM: C[128x128 tile] = A[m0:,k0:k1] * B[n0:,k0:k1]^T
// A:[M,K] row-major, B:[N,K] row-major (both K-major). 256 threads.
// SPLIT: hi/lo tf32 3-MMA emulation of fp32.
// smem rows padded to 20 floats (80B) -> conflict-free ldmatrix.
// ---------------------------------------------------------------------------
#define TILE_B  (128*20*4)      // one operand tile (hi or lo): 10240 B
#define MFRAG_B (16*20*4)       // 16 rows: 1280 B

template<bool SPLIT, class EPI>
__device__ __forceinline__ void tc_gemm(const float* __restrict__ A, int lda,
                                        const float* __restrict__ B, int ldb,
                                        int m0, int n0, int k0, int k1, EPI&& epi)
{
  extern __shared__ __align__(16) char sd[];
  const int t = threadIdx.x, l = t & 31, w = t >> 5;
  const int wm = w & 3, wn = w >> 2;          // 4 warps on M x 2 on N
  const int NT = SPLIT ? 4 : 2;
  const int STAGE = NT * TILE_B;

  // staging indices: thread -> (row, 8-float segment)
  const int arow = t >> 1, acol = (t & 1) * 8;
  const float* Ap = A + (size_t)(m0 + arow) * lda + acol;
  const float* Bp = B + (size_t)(n0 + arow) * ldb + acol;
  const uint32_t soff = (uint32_t)(arow * 20 + acol) * 4;

  // ldmatrix per-lane offsets
  const int rowA = (l & 7) + ((l >> 3) & 1) * 8;
  const int colA = ((l >> 4) & 1) * 4;
  const int rowB = (l & 7) + ((l >> 4) & 1) * 8;
  const int colB = ((l >> 3) & 1) * 4;
  const uint32_t aoff = (uint32_t)((wm * 32 + rowA) * 20 + colA) * 4;
  const uint32_t boff = (uint32_t)((wn * 64 + rowB) * 20 + colB) * 4;
  const uint32_t sbase = s2u(sd);

  float acc[2][8][4] = {};
  float4 pa0, pa1, pb0, pb1;

  const int nch = (k1 - k0) >> 4;
  pa0 = *(const float4*)(Ap + k0);     pa1 = *(const float4*)(Ap + k0 + 4);
  pb0 = *(const float4*)(Bp + k0);     pb1 = *(const float4*)(Bp + k0 + 4);

  for (int c = 0; c < nch; c++){
    char* st = sd + (c & 1) * STAGE;
    char* pAhi = st;
    char* pAlo = st + TILE_B;
    char* pBhi = st + (SPLIT ? 2 : 1) * TILE_B;
    char* pBlo = pBhi + TILE_B;

    // cvt + STS
    float4 h0 = make_float4(tf32r(pa0.x), tf32r(pa0.y), tf32r(pa0.z), tf32r(pa0.w));
    float4 h1 = make_float4(tf32r(pa1.x), tf32r(pa1.y), tf32r(pa1.z), tf32r(pa1.w));
    *(float4*)(pAhi + soff)      = h0;
    *(float4*)(pAhi + soff + 16) = h1;
    if (SPLIT){
      *(float4*)(pAlo + soff)      = make_float4(tf32r(pa0.x-h0.x), tf32r(pa0.y-h0.y),
                                                 tf32r(pa0.z-h0.z), tf32r(pa0.w-h0.w));
      *(float4*)(pAlo + soff + 16) = make_float4(tf32r(pa1.x-h1.x), tf32r(pa1.y-h1.y),
                                                 tf32r(pa1.z-h1.z), tf32r(pa1.w-h1.w));
    }
    h0 = make_float4(tf32r(pb0.x), tf32r(pb0.y), tf32r(pb0.z), tf32r(pb0.w));
    h1 = make_float4(tf32r(pb1.x), tf32r(pb1.y), tf32r(pb1.z), tf32r(pb1.w));
    *(float4*)(pBhi + soff)      = h0;
    *(float4*)(pBhi + soff + 16) = h1;
    if (SPLIT){
      *(float4*)(pBlo + soff)      = make_float4(tf32r(pb0.x-h0.x), tf32r(pb0.y-h0.y),
                                                 tf32r(pb0.z-h0.z), tf32r(pb0.w-h0.w));
      *(float4*)(pBlo + soff + 16) = make_float4(tf32r(pb1.x-h1.x), tf32r(pb1.y-h1.y),
                                                 tf32r(pb1.z-h1.z), tf32r(pb1.w-h1.w));
    }
    __syncthreads();

    // prefetch next chunk
    if (c + 1 < nch){
      const int kn = k0 + (c + 1) * 16;
      pa0 = *(const float4*)(Ap + kn);     pa1 = *(const float4*)(Ap + kn + 4);
      pb0 = *(const float4*)(Bp + kn);     pb1 = *(const float4*)(Bp + kn + 4);
    }

    // compute from smem
    const uint32_t base = sbase + (c & 1) * STAGE;
    const uint32_t uAhi = base + aoff;
    const uint32_t uAlo = uAhi + TILE_B;
    const uint32_t uBhi = base + (SPLIT ? 2 : 1) * TILE_B + boff;
    const uint32_t uBlo = uBhi + TILE_B;

    #pragma unroll
    for (int kf = 0; kf < 2; kf++){
      const uint32_t ko = kf * 32;
      uint32_t ah[2][4], al[2][4];
      ldsm4(ah[0], uAhi + ko);
      ldsm4(ah[1], uAhi + ko + MFRAG_B);
      if (SPLIT){
        ldsm4(al[0], uAlo + ko);
        ldsm4(al[1], uAlo + ko + MFRAG_B);
      }
      #pragma unroll
      for (int nf2 = 0; nf2 < 4; nf2++){
        uint32_t bh[4];
        ldsm4(bh, uBhi + ko + nf2 * MFRAG_B);
        #pragma unroll
        for (int mf = 0; mf < 2; mf++){
          mma8(acc[mf][2*nf2],     ah[mf], bh);
          mma8(acc[mf][2*nf2 + 1], ah[mf], bh + 2);
        }
        if (SPLIT){
          uint32_t bl[4];
          ldsm4(bl, uBlo + ko + nf2 * MFRAG_B);
          #pragma unroll
          for (int mf = 0; mf < 2; mf++){
            mma8(acc[mf][2*nf2],     ah[mf], bl);
            mma8(acc[mf][2*nf2 + 1], ah[mf], bl + 2);
            mma8(acc[mf][2*nf2],     al[mf], bh);
            mma8(acc[mf][2*nf2 + 1], al[mf], bh + 2);
          }
        }
      }
    }
  }
  epi(acc);
}

// store epilogue: C[m0+.., n0+..] = acc
__device__ __forceinline__ void epi_store(float (&acc)[2][8][4],
                                          float* __restrict__ C, int ldc,
                                          int m0, int n0)
{
  const int t = threadIdx.x, l = t & 31, w = t >> 5;
  const int wm = w & 3, wn = w >> 2;
  #pragma unroll
  for (int mf = 0; mf < 2; mf++){
    const int r0 = m0 + wm*32 + mf*16 + (l >> 2);
    #pragma unroll
    for (int nf = 0; nf < 8; nf++){
      const int cc = n0 + wn*64 + nf*8 + 2*(l & 3);
      *(float2*)&C[(size_t)r0*ldc + cc]       = make_float2(acc[mf][nf][0], acc[mf][nf][1]);
      *(float2*)&C[(size_t)(r0+8)*ldc + cc]   = make_float2(acc[mf][nf][2], acc[mf][nf][3]);
    }
  }
}

// ---------------------------------------------------------------------------
// Kernels
// ---------------------------------------------------------------------------
__global__ void __launch_bounds__(256)
k_proj_a(const float* __restrict__ x, const float* __restrict__ W)
{ // g_K = x @ W^T ; also writes g_Kt = (x @ W^T)^T from the same accumulators
  const int n0 = blockIdx.x*128, m0 = blockIdx.y*128;
  tc_gemm<true>(x, DM, W, DM, m0, n0, 0, DM,
    [&](float (&acc)[2][8][4]){
      epi_store(acc, g_K, DM, m0, n0);
      // transposed store: g_Kt[n][m], ld = NB*NCTX. Lanes with consecutive
      // l>>2 write 8 consecutive m -> full 32B sectors.
      const int t = threadIdx.x, l = t & 31, w = t >> 5;
      const int wm = w & 3, wn = w >> 2;
      #pragma unroll
      for (int mf = 0; mf < 2; mf++){
        const int r0 = m0 + wm*32 + mf*16 + (l >> 2);
        #pragma unroll
        for (int nf = 0; nf < 8; nf++){
          const int cc = n0 + wn*64 + nf*8 + 2*(l & 3);
          g_Kt[(size_t)cc*(NB*NCTX)     + r0]     = acc[mf][nf][0];
          g_Kt[(size_t)(cc+1)*(NB*NCTX) + r0]     = acc[mf][nf][1];
          g_Kt[(size_t)cc*(NB*NCTX)     + r0 + 8] = acc[mf][nf][2];
          g_Kt[(size_t)(cc+1)*(NB*NCTX) + r0 + 8] = acc[mf][nf][3];
        }
      }
    });
}

__global__ void __launch_bounds__(256)
k_scores_tc(const float* __restrict__ x)
{ // S = x @ K^T (lower-triangular tiles)
  const int b  = blockIdx.z;
  const int n0 = blockIdx.x*128, m0 = blockIdx.y*128;
  if (n0 > m0) return;
  const float* xb = x   + (size_t)b*NCTX*DM;
  const float* Kb = g_K + (size_t)b*NCTX*DM;
  float*       Sb = g_S + (size_t)b*NCTX*NCTX;
  tc_gemm<true>(xb, DM, Kb, DM, m0, n0, 0, DM,
    [&](float (&acc)[2][8][4]){ epi_store(acc, Sb, NCTX, m0, n0); });
}

__global__ void __launch_bounds__(256)
k_out_tc(const float* __restrict__ x, float* __restrict__ out)
{ // out = x + P @ K  (split-K over causal extent, atomic combine)
  const int b = blockIdx.z >> 2, cch = blockIdx.z & 3;
  const int n0 = blockIdx.x*128, m0 = blockIdx.y*128;
  const int kend = m0 + 128, kbeg = cch*1024;
  if (kbeg >= kend) return;
  const int k1 = kend < kbeg + 1024 ? kend : kbeg + 1024;
  const float* Pb = g_S  + (size_t)b*NCTX*NCTX;
  const float* Bt = g_Kt + (size_t)b*NCTX;     // [DM rows, ld NB*NCTX]
  tc_gemm<false>(Pb, NCTX, Bt, NB*NCTX, m0, n0, kbeg, k1,
    [&](float (&acc)[2][8][4]){
      const int t = threadIdx.x, l = t & 31, w = t >> 5;
      const int wm = w & 3, wn = w >> 2;
      #pragma unroll
      for (int mf = 0; mf < 2; mf++){
        const int r0 = m0 + wm*32 + mf*16 + (l >> 2);
        #pragma unroll
        for (int nf = 0; nf < 8; nf++){
          const int cc = n0 + wn*64 + nf*8 + 2*(l & 3);
          const size_t i0 = (size_t)b*NCTX*DM + (size_t)r0*DM + cc;
          const size_t i1 = i0 + (size_t)8*DM;
          float v0 = acc[mf][nf][0], v1 = acc[mf][nf][1];
          float v2 = acc[mf][nf][2], v3 = acc[mf][nf][3];
          if (cch == 0){ v0 += x[i0]; v1 += x[i0+1]; v2 += x[i1]; v3 += x[i1+1]; }
          atomicAdd(out + i0,     v0);
          atomicAdd(out + i0 + 1, v1);
          atomicAdd(out + i1,     v2);
          atomicAdd(out + i1 + 1, v3);
        }
      }
    });
}

// ---------------------------------------------------------------------------
// Causal softmax, in place on g_S (float4-vectorized)
// ---------------------------------------------------------------------------
__device__ __forceinline__ float blk_reduce(float v, bool is_max)
{
  __shared__ float sm[8];
  const int lane = threadIdx.x & 31, w = threadIdx.x >> 5;
  #pragma unroll
  for (int o = 16; o; o >>= 1){
    float u = __shfl_xor_sync(0xffffffffu, v, o);
    v = is_max ? fmaxf(v, u) : v + u;
  }
  if (lane == 0) sm[w] = v;
  __syncthreads();
  float r = sm[0];
  #pragma unroll
  for (int i = 1; i < 8; i++) r = is_max ? fmaxf(r, sm[i]) : r + sm[i];
  __syncthreads();
  return r;
}

__global__ void __launch_bounds__(256)
k_softmax()
{
  const int row = blockIdx.x;
  const int q   = row & (NCTX - 1);
  float* p = g_S + (size_t)row * NCTX;
  const int len  = q + 1;
  const int len4 = len >> 2;           // whole float4s
  float4* p4 = (float4*)p;

  float m = -1e30f;
  for (int i = threadIdx.x; i < len4; i += 256){
    float4 v = p4[i];
    m = fmaxf(m, fmaxf(fmaxf(v.x, v.y), fmaxf(v.z, v.w)));
  }
  for (int i = (len4 << 2) + threadIdx.x; i < len; i += 256) m = fmaxf(m, p[i]);
  m = blk_reduce(m, true);

  float s = 0.f;
  for (int i = threadIdx.x; i < len4; i += 256){
    float4 v = p4[i];
    v.x = __expf(v.x - m); v.y = __expf(v.y - m);
    v.z = __expf(v.z - m); v.w = __expf(v.w - m);
    p4[i] = v;
    s += (v.x + v.y) + (v.z + v.w);
  }
  for (int i = (len4 << 2) + threadIdx.x; i < len; i += 256){
    float e = __expf(p[i] - m);
    p[i] = e;
    s += e;
  }
  s = blk_reduce(s, false);
  const float inv = 1.f / s;

  for (int i = threadIdx.x; i < len4; i += 256){
    float4 v = p4[i];
    v.x *= inv; v.y *= inv; v.z *= inv; v.w *= inv;
    p4[i] = v;
  }
  for (int i = (len4 << 2) + threadIdx.x; i < len; i += 256) p[i] *= inv;

  // zero-fill up to the next 128 boundary so P@K can run whole tiles
  const int lenUp = (len + 127) & ~127;
  for (int i = len + threadIdx.x; i < lenUp; i += 256) p[i] = 0.f;
}

// ---------------------------------------------------------------------------
extern "C" void kernel_launch(void* const* d_in, const int* in_sizes, int n_in,
                              void* d_out, int out_size)
{
  const float* x = (const float*)d_in[0];
  const float* W = (const float*)d_in[1];
  float* out = (float*)d_out;

  const int SMEM_SPLIT = 2 * 4 * TILE_B;   // 81920
  const int SMEM_PLAIN = 2 * 2 * TILE_B;   // 40960
  cudaFuncSetAttribute(k_proj_a,    cudaFuncAttributeMaxDynamicSharedMemorySize, SMEM_SPLIT);
  cudaFuncSetAttribute(k_scores_tc, cudaFuncAttributeMaxDynamicSharedMemorySize, SMEM_SPLIT);
  cudaFuncSetAttribute(k_out_tc,    cudaFuncAttributeMaxDynamicSharedMemorySize, SMEM_PLAIN);

  cudaMemsetAsync(out, 0, (size_t)out_size * sizeof(float), 0);

  k_proj_a   <<<dim3(4, 64),       256, SMEM_SPLIT>>>(x, W);
  k_scores_tc<<<dim3(32, 32, NB),  256, SMEM_SPLIT>>>(x);
  k_softmax  <<<NB * NCTX, 256>>>();
  k_out_tc   <<<dim3(4, 32, NB*4), 256, SMEM_PLAIN>>>(x, out);
}